// round 4
// baseline (speedup 1.0000x reference)
#include <cuda_runtime.h>
#include <cuda_bf16.h>

// MeanAggregator: out[r,:] = mean over UNIQUE neighbors c of row r of embed[c,:]
// row_idx sorted ascending. D = 300 floats = 75 float4.
// Design: 2 warps per row (D-split 37/38 float4 slots), warp-synchronous dedup
// duplicated per warp (deterministic, no cross-warp sync needed).

#define AGG_D4   75
#define AGG_MAXL 192           // per-warp staged unique cap (L ~ Poisson(32))
#define AGG_MAXB 65536
#define ROWS_PB  4             // rows per block (8 warps)

__device__ int g_row_start[AGG_MAXB + 1];

// CSR row pointers by diff-scatter over the sorted row_idx (O(E), contiguous loads).
__global__ void build_row_starts(const int* __restrict__ row_idx, int E, int B) {
    int i = blockIdx.x * blockDim.x + threadIdx.x;
    if (i > E) return;
    if (i == 0) {
        int cur = row_idx[0];
        for (int v = 0; v <= cur; ++v) g_row_start[v] = 0;
    } else if (i == E) {
        int prev = row_idx[E - 1];
        for (int v = prev + 1; v <= B; ++v) g_row_start[v] = E;
    } else {
        int prev = row_idx[i - 1];
        int cur  = row_idx[i];
        for (int v = prev + 1; v <= cur; ++v) g_row_start[v] = i;
    }
}

__global__ __launch_bounds__(ROWS_PB * 64) void mean_agg_kernel(
    const int*    __restrict__ col_idx,
    const float4* __restrict__ embed4,   // [U, 75]
    float4*       __restrict__ out4,     // [B, 75]
    int B)
{
    const int w    = threadIdx.x >> 5;        // 0..7
    const int lane = threadIdx.x & 31;
    const int r    = blockIdx.x * ROWS_PB + (w >> 1);
    const int half = w & 1;
    if (r >= B) return;                       // warp-uniform

    // D-split: half 0 -> float4 slots [0,37), half 1 -> [37,75)
    const int slot_base  = half ? 37 : 0;
    const int second_cnt = half ? 6  : 5;     // slots beyond the first 32

    const int start = g_row_start[r];
    const int L     = g_row_start[r + 1] - start;

    __shared__ int s_uniq[ROWS_PB * 2][AGG_MAXL];
    int* su = s_uniq[w];

    float4 a0 = make_float4(0.f, 0.f, 0.f, 0.f);
    float4 a1 = a0;
    const unsigned lt = (1u << lane) - 1u;
    int Lu = 0;

    const float4* __restrict__ e = embed4 + slot_base + lane;
    const bool has2 = (lane < second_cnt);

    if (L <= AGG_MAXL) {
        // ---- warp-synchronous order-preserving dedup (identical in both halves) ----
        for (int base = 0; base < L; base += 32) {
            int  j   = base + lane;
            bool inb = (j < L);
            int  c   = inb ? col_idx[start + j] : -(lane + 1);
            unsigned peers = __match_any_sync(0xffffffffu, c);
            bool valid = inb && ((peers & lt) == 0);
            if (valid) {
                for (int i = 0; i < Lu; ++i)
                    if (su[i] == c) { valid = false; break; }
            }
            unsigned m = __ballot_sync(0xffffffffu, valid);
            if (valid) su[Lu + __popc(m & lt)] = c;
            Lu += __popc(m);
            __syncwarp();
        }

        // ---- gather: unroll-4, up to 8 independent LDG.128 in flight per warp ----
        int j = 0;
        for (; j + 4 <= Lu; j += 4) {
            const float4* p0 = e + (size_t)su[j]     * AGG_D4;
            const float4* p1 = e + (size_t)su[j + 1] * AGG_D4;
            const float4* p2 = e + (size_t)su[j + 2] * AGG_D4;
            const float4* p3 = e + (size_t)su[j + 3] * AGG_D4;
            float4 x0 = p0[0], x1 = p1[0], x2 = p2[0], x3 = p3[0];
            if (has2) {
                float4 y0 = p0[32], y1 = p1[32], y2 = p2[32], y3 = p3[32];
                a1.x += y0.x + y1.x + y2.x + y3.x;
                a1.y += y0.y + y1.y + y2.y + y3.y;
                a1.z += y0.z + y1.z + y2.z + y3.z;
                a1.w += y0.w + y1.w + y2.w + y3.w;
            }
            a0.x += x0.x + x1.x + x2.x + x3.x;
            a0.y += x0.y + x1.y + x2.y + x3.y;
            a0.z += x0.z + x1.z + x2.z + x3.z;
            a0.w += x0.w + x1.w + x2.w + x3.w;
        }
        for (; j < Lu; ++j) {
            const float4* p = e + (size_t)su[j] * AGG_D4;
            float4 x = p[0];
            if (has2) {
                float4 y = p[32];
                a1.x += y.x; a1.y += y.y; a1.z += y.z; a1.w += y.w;
            }
            a0.x += x.x; a0.y += x.y; a0.z += x.z; a0.w += x.w;
        }
    } else {
        // Unreachable-for-this-data fallback: O(L^2) global dedup, direct accumulate.
        for (int j = 0; j < L; ++j) {
            int c = col_idx[start + j];
            bool valid = true;
            for (int i = 0; i < j; ++i)
                if (col_idx[start + i] == c) { valid = false; break; }
            if (!valid) continue;
            ++Lu;
            const float4* p = e + (size_t)c * AGG_D4;
            float4 x = p[0];
            if (has2) {
                float4 y = p[32];
                a1.x += y.x; a1.y += y.y; a1.z += y.z; a1.w += y.w;
            }
            a0.x += x.x; a0.y += x.y; a0.z += x.z; a0.w += x.w;
        }
    }

    const float inv = 1.0f / fmaxf((float)Lu, 1e-8f);
    float4* o = out4 + (size_t)r * AGG_D4 + slot_base + lane;
    float4 t;
    t.x = a0.x * inv; t.y = a0.y * inv; t.z = a0.z * inv; t.w = a0.w * inv;
    o[0] = t;
    if (has2) {
        t.x = a1.x * inv; t.y = a1.y * inv; t.z = a1.z * inv; t.w = a1.w * inv;
        o[32] = t;
    }
}

extern "C" void kernel_launch(void* const* d_in, const int* in_sizes, int n_in,
                              void* d_out, int out_size) {
    const int*   row_idx = (const int*)  d_in[0];
    const int*   col_idx = (const int*)  d_in[1];
    const float* embed   = (const float*)d_in[2];
    float*       out     = (float*)      d_out;

    const int E = in_sizes[0];
    const int B = out_size / 300;

    build_row_starts<<<(E + 1 + 255) / 256, 256>>>(row_idx, E, B);
    mean_agg_kernel<<<(B + ROWS_PB - 1) / ROWS_PB, ROWS_PB * 64>>>(
        col_idx, (const float4*)embed, (float4*)out, B);
}